// round 15
// baseline (speedup 1.0000x reference)
#include <cuda_runtime.h>
#include <cuda_fp16.h>
#include <cuda_bf16.h>
#include <cstdint>

// Problem constants (fixed by the reference).
constexpr int B = 8, C = 3, H = 720, W = 1280;
constexpr int HW = H * W;            // 921600
constexpr int NPIX = B * HW;         // 7372800
constexpr int CHW = C * HW;

// sA[pix]  : half2 (ch0, ch1) per destination pixel.  29.5 MB
// sB       : ch2 pair-packed parity banks. Bank0 word k = (ch2[2k], ch2[2k+1]);
//            bank1 word NB+1+k = (ch2[2k+1], ch2[2k+2]); pad slots absorb the
//            q=-1 / q=NPIX-1 edges. 29.5 MB
// Both zeroed upfront each launch via graph memset nodes: the fill stores
// double as the L2 prefetch of the atomic target (DRAM-miss atomics are ~2x
// slower than L2-hit; deferring the zero loses residency across the replay
// boundary — R7/R10).
constexpr int NB = NPIX / 2 + 1;
constexpr int SB_WORDS = 2 * NB + 2;      // multiple of 4
__device__ __align__(16) unsigned int g_sA[NPIX];
__device__ __align__(16) unsigned int g_sB[SB_WORDS];

__device__ __forceinline__ void red_add_f16x2(unsigned int* p, unsigned int v) {
    asm volatile("red.global.add.noftz.f16x2 [%0], %1;"
                 :: "l"(p), "r"(v) : "memory");
}
__device__ __forceinline__ unsigned int pack2(float a, float b) {
    __half2 h = __floats2half2_rn(a, b);
    return *reinterpret_cast<unsigned int*>(&h);
}
__device__ __forceinline__ float lo_f(unsigned int u) {
    return __low2float(*reinterpret_cast<__half2*>(&u));
}
__device__ __forceinline__ float hi_f(unsigned int u) {
    return __high2float(*reinterpret_cast<__half2*>(&u));
}

// ---------------------------------------------------------------------------
// Pass 1 (memset nodes in kernel_launch): zero sA and sB.
// ---------------------------------------------------------------------------

// ---------------------------------------------------------------------------
// Pass 2: forward-warp scatter. Exactly 3 f16x2 REDs per valid corner row
// (6 L2 atomic elements per source pixel — the packing floor). Streaming
// inputs are read with .cs (evict-first) so they do not displace the
// L2-resident scratch.
// ---------------------------------------------------------------------------
__global__ __launch_bounds__(256)
void forward_warp_kernel(const float* __restrict__ im0,
                         const float2* __restrict__ flow) {
    int p = blockIdx.x * blockDim.x + threadIdx.x;
    if (p >= NPIX) return;

    int b = p / HW;
    int r = p - b * HW;
    int h = r / W;
    int w = r - h * W;

    float2 f = __ldcs(flow + p);
    float x = (float)w + f.x;
    float y = (float)h + f.y;

    float x0f = floorf(x);
    float y0f = floorf(y);
    float wx1 = x - x0f;
    float wx0 = 1.0f - wx1;
    float wy1 = y - y0f;
    float wy0 = 1.0f - wy1;

    int xi = (int)x0f;
    if (x0f < -1.0f || x0f > (float)(W - 1)) return;   // both x-corners OOB
    if (x0f < 0.0f)           wx0 = 0.0f;              // xi == -1
    if (x0f > (float)(W - 2)) wx1 = 0.0f;              // xi == W-1

    int ibase = b * CHW + r;
    float v0 = __ldcs(im0 + ibase);
    float v1 = __ldcs(im0 + ibase + HW);
    float v2 = __ldcs(im0 + ibase + 2 * HW);

    int pbase = b * HW;

    #pragma unroll
    for (int cy = 0; cy < 2; ++cy) {
        float yc = y0f + (float)cy;
        if (yc < 0.0f || yc > (float)(H - 1)) continue;
        int yi = (int)yc;
        float wy = cy ? wy1 : wy0;
        float wa = wy * wx0;                 // weight of corner q   (= x0)
        float wb = wy * wx1;                 // weight of corner q+1 (= x0+1)

        int q  = pbase + yi * W + xi;        // in [-1, NPIX-1]
        int qa = max(q, 0);                  // clamped: wa==0 when clamp fires
        int qb = min(q + 1, NPIX - 1);       // clamped: wb==0 when clamp fires

        red_add_f16x2(g_sA + qa, pack2(wa * v0, wa * v1));
        red_add_f16x2(g_sA + qb, pack2(wb * v0, wb * v1));

        // ch2 pair word: bank by parity of q; slot covers (q:lo, q+1:hi).
        int par = q & 1;                     // q=-1 -> par=1
        int off = par * (NB + 1) + (q >> 1) + par;
        red_add_f16x2(g_sB + off, pack2(wa * v2, wb * v2));
    }
}

// ---------------------------------------------------------------------------
// Pass 3: gather and write all three f32 planes. Thread j -> pixels 2j, 2j+1.
// Scratch is read-once (.cs); out is write-once (.cs) and never re-read.
//   ch2[2j]   = lo(bank0[j]) + hi(bank1[NB+1 + j])
//   ch2[2j+1] = hi(bank0[j]) + lo(bank1[NB+1 + j + 1])
// ---------------------------------------------------------------------------
__global__ __launch_bounds__(256)
void finalize_kernel(float* __restrict__ out) {
    int j = blockIdx.x * blockDim.x + threadIdx.x;
    constexpr int N2 = NPIX / 2;
    if (j >= N2) return;

    uint2 a = __ldcs(reinterpret_cast<const uint2*>(g_sA) + j);
    unsigned int w0 = __ldcs(g_sB + j);                  // bank0 slot j
    unsigned int w1 = __ldcs(g_sB + NB + 1 + j);         // bank1 slot j
    unsigned int w2 = __ldcs(g_sB + NB + 1 + j + 1);     // bank1 slot j+1

    __half2 p0 = *reinterpret_cast<__half2*>(&a.x);
    __half2 p1 = *reinterpret_cast<__half2*>(&a.y);

    float c0a = __low2float(p0);
    float c1a = __high2float(p0);
    float c0b = __low2float(p1);
    float c1b = __high2float(p1);
    float c2a = lo_f(w0) + hi_f(w1);
    float c2b = hi_f(w0) + lo_f(w2);

    int i = j * 2;
    int b = i / HW;
    int r = i - b * HW;                                  // even
    float* base = out + b * CHW + r;
    __stcs(reinterpret_cast<float2*>(base),          make_float2(c0a, c0b));
    __stcs(reinterpret_cast<float2*>(base + HW),     make_float2(c1a, c1b));
    __stcs(reinterpret_cast<float2*>(base + 2 * HW), make_float2(c2a, c2b));
}

extern "C" void kernel_launch(void* const* d_in, const int* in_sizes, int n_in,
                              void* d_out, int out_size) {
    const float*  im0  = (const float*)d_in[0];
    const float2* flow = (const float2*)d_in[1];
    float* out = (float*)d_out;

    // Zero scratch via graph memset nodes (driver fill path, no SM launch).
    // cudaGetSymbolAddress is a host-side query: no allocation, no stream op.
    void *pA, *pB;
    cudaGetSymbolAddress(&pA, g_sA);
    cudaGetSymbolAddress(&pB, g_sB);
    cudaMemsetAsync(pA, 0, sizeof(g_sA));
    cudaMemsetAsync(pB, 0, sizeof(g_sB));

    int threads = 256;
    forward_warp_kernel<<<(NPIX + threads - 1) / threads, threads>>>(im0, flow);
    finalize_kernel<<<(NPIX / 2 + threads - 1) / threads, threads>>>(out);
}

// round 16
// speedup vs baseline: 1.0111x; 1.0111x over previous
#include <cuda_runtime.h>
#include <cuda_fp16.h>
#include <cuda_bf16.h>
#include <cstdint>

// Problem constants (fixed by the reference).
constexpr int B = 8, C = 3, H = 720, W = 1280;
constexpr int HW = H * W;            // 921600
constexpr int NPIX = B * HW;         // 7372800
constexpr int CHW = C * HW;

// sA[pix]  : half2 (ch0, ch1) per destination pixel.  29.5 MB
// sB       : ch2 pair-packed parity banks. Bank0 word k = (ch2[2k], ch2[2k+1]);
//            bank1 word NB+1+k = (ch2[2k+1], ch2[2k+2]); pad slots absorb the
//            q=-1 / q=NPIX-1 edges. 29.5 MB
// Both zeroed upfront each launch by the SM zero kernel (faster than memset
// nodes, R15): the stores double as an L2 prefetch of the atomic target
// (DRAM-miss atomics are ~2x slower than L2-hit; deferring the zero loses
// residency across the replay boundary — R7/R10).
constexpr int NB = NPIX / 2 + 1;
constexpr int SB_WORDS = 2 * NB + 2;      // multiple of 4
__device__ __align__(16) unsigned int g_sA[NPIX];
__device__ __align__(16) unsigned int g_sB[SB_WORDS];

__device__ __forceinline__ void red_add_f16x2(unsigned int* p, unsigned int v) {
    asm volatile("red.global.add.noftz.f16x2 [%0], %1;"
                 :: "l"(p), "r"(v) : "memory");
}
__device__ __forceinline__ unsigned int pack2(float a, float b) {
    __half2 h = __floats2half2_rn(a, b);
    return *reinterpret_cast<unsigned int*>(&h);
}
__device__ __forceinline__ float lo_f(unsigned int u) {
    return __low2float(*reinterpret_cast<__half2*>(&u));
}
__device__ __forceinline__ float hi_f(unsigned int u) {
    return __high2float(*reinterpret_cast<__half2*>(&u));
}

// ---------------------------------------------------------------------------
// Pass 1: zero both scratch regions (out is fully overwritten by finalize).
// ---------------------------------------------------------------------------
__global__ __launch_bounds__(256)
void zero_kernel() {
    constexpr int NA4 = NPIX / 4;
    constexpr int NB4 = SB_WORDS / 4;
    int j = blockIdx.x * blockDim.x + threadIdx.x;
    if (j < NA4) {
        reinterpret_cast<uint4*>(g_sA)[j] = make_uint4(0u, 0u, 0u, 0u);
    } else if (j < NA4 + NB4) {
        reinterpret_cast<uint4*>(g_sB)[j - NA4] = make_uint4(0u, 0u, 0u, 0u);
    }
}

// ---------------------------------------------------------------------------
// Pass 2: forward-warp scatter. Exactly 3 f16x2 REDs per valid corner row
// (6 L2 atomic elements per source pixel — the packing floor; runs at ~96%
// of the measured L2-atomic element roofline). Streaming inputs are read
// with .cs (evict-first) so they do not displace the L2-resident scratch.
// ---------------------------------------------------------------------------
__global__ __launch_bounds__(256)
void forward_warp_kernel(const float* __restrict__ im0,
                         const float2* __restrict__ flow) {
    int p = blockIdx.x * blockDim.x + threadIdx.x;
    if (p >= NPIX) return;

    int b = p / HW;
    int r = p - b * HW;
    int h = r / W;
    int w = r - h * W;

    float2 f = __ldcs(flow + p);
    float x = (float)w + f.x;
    float y = (float)h + f.y;

    float x0f = floorf(x);
    float y0f = floorf(y);
    float wx1 = x - x0f;
    float wx0 = 1.0f - wx1;
    float wy1 = y - y0f;
    float wy0 = 1.0f - wy1;

    int xi = (int)x0f;
    if (x0f < -1.0f || x0f > (float)(W - 1)) return;   // both x-corners OOB
    if (x0f < 0.0f)           wx0 = 0.0f;              // xi == -1
    if (x0f > (float)(W - 2)) wx1 = 0.0f;              // xi == W-1

    int ibase = b * CHW + r;
    float v0 = __ldcs(im0 + ibase);
    float v1 = __ldcs(im0 + ibase + HW);
    float v2 = __ldcs(im0 + ibase + 2 * HW);

    int pbase = b * HW;

    #pragma unroll
    for (int cy = 0; cy < 2; ++cy) {
        float yc = y0f + (float)cy;
        if (yc < 0.0f || yc > (float)(H - 1)) continue;
        int yi = (int)yc;
        float wy = cy ? wy1 : wy0;
        float wa = wy * wx0;                 // weight of corner q   (= x0)
        float wb = wy * wx1;                 // weight of corner q+1 (= x0+1)

        int q  = pbase + yi * W + xi;        // in [-1, NPIX-1]
        int qa = max(q, 0);                  // clamped: wa==0 when clamp fires
        int qb = min(q + 1, NPIX - 1);       // clamped: wb==0 when clamp fires

        red_add_f16x2(g_sA + qa, pack2(wa * v0, wa * v1));
        red_add_f16x2(g_sA + qb, pack2(wb * v0, wb * v1));

        // ch2 pair word: bank by parity of q; slot covers (q:lo, q+1:hi).
        int par = q & 1;                     // q=-1 -> par=1
        int off = par * (NB + 1) + (q >> 1) + par;
        red_add_f16x2(g_sB + off, pack2(wa * v2, wb * v2));
    }
}

// ---------------------------------------------------------------------------
// Pass 3: gather and write all three f32 planes. Thread j -> pixels 2j, 2j+1.
// Scratch is read-once (.cs); out is write-once (.cs) and never re-read.
//   ch2[2j]   = lo(bank0[j]) + hi(bank1[NB+1 + j])
//   ch2[2j+1] = hi(bank0[j]) + lo(bank1[NB+1 + j + 1])
// ---------------------------------------------------------------------------
__global__ __launch_bounds__(256)
void finalize_kernel(float* __restrict__ out) {
    int j = blockIdx.x * blockDim.x + threadIdx.x;
    constexpr int N2 = NPIX / 2;
    if (j >= N2) return;

    uint2 a = __ldcs(reinterpret_cast<const uint2*>(g_sA) + j);
    unsigned int w0 = __ldcs(g_sB + j);                  // bank0 slot j
    unsigned int w1 = __ldcs(g_sB + NB + 1 + j);         // bank1 slot j
    unsigned int w2 = __ldcs(g_sB + NB + 1 + j + 1);     // bank1 slot j+1

    __half2 p0 = *reinterpret_cast<__half2*>(&a.x);
    __half2 p1 = *reinterpret_cast<__half2*>(&a.y);

    float c0a = __low2float(p0);
    float c1a = __high2float(p0);
    float c0b = __low2float(p1);
    float c1b = __high2float(p1);
    float c2a = lo_f(w0) + hi_f(w1);
    float c2b = hi_f(w0) + lo_f(w2);

    int i = j * 2;
    int b = i / HW;
    int r = i - b * HW;                                  // even
    float* base = out + b * CHW + r;
    __stcs(reinterpret_cast<float2*>(base),          make_float2(c0a, c0b));
    __stcs(reinterpret_cast<float2*>(base + HW),     make_float2(c1a, c1b));
    __stcs(reinterpret_cast<float2*>(base + 2 * HW), make_float2(c2a, c2b));
}

extern "C" void kernel_launch(void* const* d_in, const int* in_sizes, int n_in,
                              void* d_out, int out_size) {
    const float*  im0  = (const float*)d_in[0];
    const float2* flow = (const float2*)d_in[1];
    float* out = (float*)d_out;

    int threads = 256;
    constexpr int ZERO_ITEMS = NPIX / 4 + SB_WORDS / 4;
    zero_kernel<<<(ZERO_ITEMS + threads - 1) / threads, threads>>>();
    forward_warp_kernel<<<(NPIX + threads - 1) / threads, threads>>>(im0, flow);
    finalize_kernel<<<(NPIX / 2 + threads - 1) / threads, threads>>>(out);
}

// round 17
// speedup vs baseline: 1.0139x; 1.0028x over previous
#include <cuda_runtime.h>
#include <cuda_fp16.h>
#include <cuda_bf16.h>
#include <cstdint>

// Problem constants (fixed by the reference).
constexpr int B = 8, C = 3, H = 720, W = 1280;
constexpr int HW = H * W;            // 921600
constexpr int NPIX = B * HW;         // 7372800
constexpr int CHW = C * HW;

// sA[pix]  : half2 (ch0, ch1) per destination pixel.  29.5 MB
// sB       : ch2 pair-packed parity banks. Bank0 word k = (ch2[2k], ch2[2k+1]);
//            bank1 word NB+1+k = (ch2[2k+1], ch2[2k+2]); pad slots absorb the
//            q=-1 / q=NPIX-1 edges. 29.5 MB
// Both zeroed upfront each launch: the stores double as an L2 prefetch of the
// atomic target (DRAM-miss atomics are ~2x slower than L2-hit; deferring the
// zero loses residency across the replay boundary — R7/R10).
constexpr int NB = NPIX / 2 + 1;
constexpr int SB_WORDS = 2 * NB + 2;      // multiple of 4
__device__ __align__(16) unsigned int g_sA[NPIX];
__device__ __align__(16) unsigned int g_sB[SB_WORDS];

__device__ __forceinline__ void red_add_f16x2(unsigned int* p, unsigned int v) {
    asm volatile("red.global.add.noftz.f16x2 [%0], %1;"
                 :: "l"(p), "r"(v) : "memory");
}
__device__ __forceinline__ unsigned int pack2(float a, float b) {
    __half2 h = __floats2half2_rn(a, b);
    return *reinterpret_cast<unsigned int*>(&h);
}
__device__ __forceinline__ float lo_f(unsigned int u) {
    return __low2float(*reinterpret_cast<__half2*>(&u));
}
__device__ __forceinline__ float hi_f(unsigned int u) {
    return __high2float(*reinterpret_cast<__half2*>(&u));
}

// ---------------------------------------------------------------------------
// Pass 1: zero both scratch regions (out is fully overwritten by finalize).
// Grid-stride, 8 independent uint4 stores per thread: 8x fewer blocks than
// the 1-store-per-thread version, whose block launch/retire rate (occ 35%,
// issue 19%, DRAM 3%) paced the pass.
// ---------------------------------------------------------------------------
constexpr int ZUNROLL = 8;
constexpr int ZTHREADS = 256;
constexpr int ZTOTAL4 = NPIX / 4 + SB_WORDS / 4;                 // uint4 items
constexpr int ZBLOCKS = (ZTOTAL4 + ZTHREADS * ZUNROLL - 1) / (ZTHREADS * ZUNROLL);

__global__ __launch_bounds__(ZTHREADS)
void zero_kernel() {
    constexpr int NA4 = NPIX / 4;
    int base = blockIdx.x * (ZTHREADS * ZUNROLL) + threadIdx.x;
    #pragma unroll
    for (int u = 0; u < ZUNROLL; ++u) {
        int j = base + u * ZTHREADS;
        if (j < NA4) {
            reinterpret_cast<uint4*>(g_sA)[j] = make_uint4(0u, 0u, 0u, 0u);
        } else if (j < ZTOTAL4) {
            reinterpret_cast<uint4*>(g_sB)[j - NA4] = make_uint4(0u, 0u, 0u, 0u);
        }
    }
}

// ---------------------------------------------------------------------------
// Pass 2: forward-warp scatter. Exactly 3 f16x2 REDs per valid corner row
// (6 L2 atomic elements per source pixel — the packing floor; runs at ~96%
// of the measured L2-atomic element roofline). Streaming inputs are read
// with .cs (evict-first) so they do not displace the L2-resident scratch.
// ---------------------------------------------------------------------------
__global__ __launch_bounds__(256)
void forward_warp_kernel(const float* __restrict__ im0,
                         const float2* __restrict__ flow) {
    int p = blockIdx.x * blockDim.x + threadIdx.x;
    if (p >= NPIX) return;

    int b = p / HW;
    int r = p - b * HW;
    int h = r / W;
    int w = r - h * W;

    float2 f = __ldcs(flow + p);
    float x = (float)w + f.x;
    float y = (float)h + f.y;

    float x0f = floorf(x);
    float y0f = floorf(y);
    float wx1 = x - x0f;
    float wx0 = 1.0f - wx1;
    float wy1 = y - y0f;
    float wy0 = 1.0f - wy1;

    int xi = (int)x0f;
    if (x0f < -1.0f || x0f > (float)(W - 1)) return;   // both x-corners OOB
    if (x0f < 0.0f)           wx0 = 0.0f;              // xi == -1
    if (x0f > (float)(W - 2)) wx1 = 0.0f;              // xi == W-1

    int ibase = b * CHW + r;
    float v0 = __ldcs(im0 + ibase);
    float v1 = __ldcs(im0 + ibase + HW);
    float v2 = __ldcs(im0 + ibase + 2 * HW);

    int pbase = b * HW;

    #pragma unroll
    for (int cy = 0; cy < 2; ++cy) {
        float yc = y0f + (float)cy;
        if (yc < 0.0f || yc > (float)(H - 1)) continue;
        int yi = (int)yc;
        float wy = cy ? wy1 : wy0;
        float wa = wy * wx0;                 // weight of corner q   (= x0)
        float wb = wy * wx1;                 // weight of corner q+1 (= x0+1)

        int q  = pbase + yi * W + xi;        // in [-1, NPIX-1]
        int qa = max(q, 0);                  // clamped: wa==0 when clamp fires
        int qb = min(q + 1, NPIX - 1);       // clamped: wb==0 when clamp fires

        red_add_f16x2(g_sA + qa, pack2(wa * v0, wa * v1));
        red_add_f16x2(g_sA + qb, pack2(wb * v0, wb * v1));

        // ch2 pair word: bank by parity of q; slot covers (q:lo, q+1:hi).
        int par = q & 1;                     // q=-1 -> par=1
        int off = par * (NB + 1) + (q >> 1) + par;
        red_add_f16x2(g_sB + off, pack2(wa * v2, wb * v2));
    }
}

// ---------------------------------------------------------------------------
// Pass 3: gather and write all three f32 planes. Thread j -> pixels 2j, 2j+1.
// Scratch is read-once (.cs); out is write-once (.cs) and never re-read.
//   ch2[2j]   = lo(bank0[j]) + hi(bank1[NB+1 + j])
//   ch2[2j+1] = hi(bank0[j]) + lo(bank1[NB+1 + j + 1])
// ---------------------------------------------------------------------------
__global__ __launch_bounds__(256)
void finalize_kernel(float* __restrict__ out) {
    int j = blockIdx.x * blockDim.x + threadIdx.x;
    constexpr int N2 = NPIX / 2;
    if (j >= N2) return;

    uint2 a = __ldcs(reinterpret_cast<const uint2*>(g_sA) + j);
    unsigned int w0 = __ldcs(g_sB + j);                  // bank0 slot j
    unsigned int w1 = __ldcs(g_sB + NB + 1 + j);         // bank1 slot j
    unsigned int w2 = __ldcs(g_sB + NB + 1 + j + 1);     // bank1 slot j+1

    __half2 p0 = *reinterpret_cast<__half2*>(&a.x);
    __half2 p1 = *reinterpret_cast<__half2*>(&a.y);

    float c0a = __low2float(p0);
    float c1a = __high2float(p0);
    float c0b = __low2float(p1);
    float c1b = __high2float(p1);
    float c2a = lo_f(w0) + hi_f(w1);
    float c2b = hi_f(w0) + lo_f(w2);

    int i = j * 2;
    int b = i / HW;
    int r = i - b * HW;                                  // even
    float* base = out + b * CHW + r;
    __stcs(reinterpret_cast<float2*>(base),          make_float2(c0a, c0b));
    __stcs(reinterpret_cast<float2*>(base + HW),     make_float2(c1a, c1b));
    __stcs(reinterpret_cast<float2*>(base + 2 * HW), make_float2(c2a, c2b));
}

extern "C" void kernel_launch(void* const* d_in, const int* in_sizes, int n_in,
                              void* d_out, int out_size) {
    const float*  im0  = (const float*)d_in[0];
    const float2* flow = (const float2*)d_in[1];
    float* out = (float*)d_out;

    int threads = 256;
    zero_kernel<<<ZBLOCKS, ZTHREADS>>>();
    forward_warp_kernel<<<(NPIX + threads - 1) / threads, threads>>>(im0, flow);
    finalize_kernel<<<(NPIX / 2 + threads - 1) / threads, threads>>>(out);
}